// round 16
// baseline (speedup 1.0000x reference)
#include <cuda_runtime.h>
#include <cuda_fp16.h>

// Problem constants
#define B_    16
#define CIN   8
#define COUT  32
#define DIN   48
#define DOUT  46
#define TPB   384     // 12 warps: 3 w-tiles x 4 h-rows
#define NCHK  14      // k16 chunks (27 taps + 1 pad, c = ic-pair axis)
#define WSTR  40      // w2_s slot stride (32 + 8 pad, conflict-free B)
#define ND    2       // d-outputs per warp (R14-proven optimum)

// x2 tile: [icpair 4][plane 4][hh 6][col 50] + 8 pad words per icpair
// XIC2 = 1208: 1208 mod 32 = 24 -> icp lane groups {0,24,16,8}: conflict-free
#define XCW   50
#define XPL   (6 * XCW)       // 300 (plane stride)
#define XIC2  1208            // 4*300 + 8 pad
#define X2SZ  (4 * XIC2)      // 4832

// smem word offsets
#define SO_X2   0
#define SO_W    X2SZ                   // 4832
#define WSZ     (112 * WSTR)           // 4480
#define SO_B    (SO_W + WSZ)           // 9312
#define SO_RED  (SO_B + 32)            // 9344
#define SMEM_WORDS (SO_RED + 64)       // 9408 -> 37632 bytes

#define NPOS_F (46.f * 46.f * 46.f)
#define EPSGN  1e-5f

typedef unsigned long long u64;

__device__ float    g_sums[B_ * 64];
__device__ unsigned g_w2[WSZ];   // packed half2 weights [slot][40]

__device__ __forceinline__ unsigned packh2(float a, float b) {
    __half2 h = __floats2half2_rn(a, b);   // lo=a, hi=b
    return *(unsigned*)&h;
}

__device__ __forceinline__ void mma_f16(float* c, const unsigned* a, const unsigned* b) {
    asm volatile(
        "mma.sync.aligned.m16n8k16.row.col.f32.f16.f16.f32 "
        "{%0,%1,%2,%3}, {%4,%5,%6,%7}, {%8,%9}, {%0,%1,%2,%3};"
        : "+f"(c[0]), "+f"(c[1]), "+f"(c[2]), "+f"(c[3])
        : "r"(a[0]), "r"(a[1]), "r"(a[2]), "r"(a[3]), "r"(b[0]), "r"(b[1]));
}

// tap -> x2 word offset (tap 27 = pad -> 0; weights are zero there)
__host__ __device__ constexpr int tapoff(int tap) {
    return (tap < 27) ? (tap / 9) * XPL + ((tap % 9) / 3) * XCW + (tap % 3) : 0;
}

// ---------------------------------------------------------------------------
// Slot map (R14-proven): s in [0,112): cc = s>>3, c = s&3 (= ic-pair),
// half = (s>>2)&1; tap = 2*cc + half. Weight half2 = ic {2c, 2c+1} at tap.
// ---------------------------------------------------------------------------
__global__ void prep_kernel(const float* __restrict__ w)
{
    int t = threadIdx.x;
    if (t < B_ * 64) g_sums[t] = 0.f;
    for (int i = t; i < WSZ; i += 1024) {
        int n = i % WSTR;
        int s = i / WSTR;
        int c   = s & 3;
        int tap = 2 * (s >> 3) + ((s >> 2) & 1);
        float wa = 0.f, wb = 0.f;
        if (tap < 27 && n < COUT) {
            wa = w[(n * CIN + 2 * c)     * 27 + tap];
            wb = w[(n * CIN + 2 * c + 1) * 27 + tap];
        }
        g_w2[i] = packh2(wa, wb);
    }
}

// ---------------------------------------------------------------------------
// Implicit-GEMM conv3d (fp16 m16n8k16), ND=2, constexpr tap offsets
// grid = (12 h-chunks, 23 d-pairs, 16 b), block = 384
// ---------------------------------------------------------------------------
extern __shared__ unsigned smem_u[];

__global__ void __launch_bounds__(TPB)
conv_mma_kernel(const float* __restrict__ x, const float* __restrict__ bias)
{
    unsigned* x2_s = smem_u + SO_X2;
    unsigned* w2_s = smem_u + SO_W;
    float* b_s   = (float*)(smem_u + SO_B);
    float* s_red = (float*)(smem_u + SO_RED);

    const int b   = blockIdx.z;
    const int db  = blockIdx.y;          // d outputs 2db, 2db+1 (< 46)
    const int h0  = blockIdx.x * 4;
    const int tid = threadIdx.x;

    // --- weights: coalesced uint4 copy (1120 uint4) ---
    {
        const uint4* src = (const uint4*)g_w2;
        uint4* dst = (uint4*)w2_s;
        for (int i = tid; i < WSZ / 4; i += TPB) dst[i] = src[i];
    }
    if (tid < 64) s_red[tid] = 0.f;
    if (tid < COUT) b_s[tid] = bias[tid];

    // --- x2 tile: 96 rows x 4 col-chunks, all 384 threads active ---
    {
        int row = tid >> 2, q4 = tid & 3;    // row = icp*24 + pl*6 + hh
        int icp = row / 24, rem = row % 24;
        int pl  = rem / 6,  hh  = rem % 6;
        int hg  = h0 + hh;
        int dg  = 2 * db + pl;               // <= 47, in-bounds
        float xa[12], xb[12];
        if (hg < DIN) {
            const float4* rowA = (const float4*)
                &x[(((b * CIN + 2 * icp)     * DIN + dg) * DIN + hg) * DIN] + 3 * q4;
            const float4* rowB = (const float4*)
                &x[(((b * CIN + 2 * icp + 1) * DIN + dg) * DIN + hg) * DIN] + 3 * q4;
            #pragma unroll
            for (int q = 0; q < 3; q++) {
                float4 va = rowA[q], vb = rowB[q];
                xa[4*q] = va.x; xa[4*q+1] = va.y; xa[4*q+2] = va.z; xa[4*q+3] = va.w;
                xb[4*q] = vb.x; xb[4*q+1] = vb.y; xb[4*q+2] = vb.z; xb[4*q+3] = vb.w;
            }
        } else {
            #pragma unroll
            for (int q = 0; q < 12; q++) { xa[q] = 0.f; xb[q] = 0.f; }
        }
        u64* base = (u64*)&x2_s[icp * XIC2 + rem * XCW];   // even word base
        u64* dst  = base + 6 * q4;
        #pragma unroll
        for (int j = 0; j < 6; j++) {
            unsigned lo = packh2(xa[2*j],     xb[2*j]);
            unsigned hi = packh2(xa[2*j + 1], xb[2*j + 1]);
            dst[j] = (u64)lo | ((u64)hi << 32);
        }
        if (q4 == 3) dst[6] = 0ull;          // cols 48,49 pad
    }
    __syncthreads();

    const int wid = tid >> 5, lane = tid & 31;
    const int grp = lane >> 2, c = lane & 3;
    const int wt  = wid % 3,  hp = wid / 3;     // w-tile (16 wide), h-row
    const int w0  = wt * 16;

    float acc[ND][4][4];
    #pragma unroll
    for (int m = 0; m < ND; m++)
        #pragma unroll
        for (int n = 0; n < 4; n++)
            #pragma unroll
            for (int k = 0; k < 4; k++) acc[m][n][k] = 0.f;

    const int xb1 = c * XIC2 + hp * XCW + w0 + grp;   // A base (+tapoff imm)
    const int wb1 = c * WSTR + grp;                    // B base

    // ---- K loop, fully unrolled: tap offsets are immediates, no roff LDS ----
    #pragma unroll
    for (int cc = 0; cc < NCHK; cc++) {
        const int P1w = (8 * cc) * WSTR + wb1;
        unsigned bf[4][2];
        #pragma unroll
        for (int nt = 0; nt < 4; nt++) {
            bf[nt][0] = w2_s[P1w + nt * 8];
            bf[nt][1] = w2_s[P1w + 4 * WSTR + nt * 8];
        }
        const int A1 = xb1 + tapoff(2 * cc);
        const int A2 = xb1 + tapoff(2 * cc + 1);
        #pragma unroll
        for (int dd = 0; dd < ND; dd++) {
            const int o = dd * XPL;
            unsigned af[4];
            af[0] = x2_s[A1 + o];
            af[1] = x2_s[A1 + o + 8];
            af[2] = x2_s[A2 + o];
            af[3] = x2_s[A2 + o + 8];
            #pragma unroll
            for (int nt = 0; nt < 4; nt++)
                mma_f16(acc[dd][nt], af, bf[nt]);
        }
    }

    // --- bias + hardswish + masked channel sums (d always valid) ---
    const bool vh0  = (h0 + hp) < DOUT;
    const bool vw[2] = { vh0 && (w0 + grp) < DOUT, vh0 && (w0 + grp + 8) < DOUT };

    float sv[8], s2[8];
    #pragma unroll
    for (int i = 0; i < 8; i++) { sv[i] = 0.f; s2[i] = 0.f; }

    #pragma unroll
    for (int dd = 0; dd < ND; dd++) {
        #pragma unroll
        for (int half = 0; half < 2; half++) {
            const bool valid = vw[half];
            #pragma unroll
            for (int nt = 0; nt < 4; nt++) {
                #pragma unroll
                for (int pr = 0; pr < 2; pr++) {
                    int ch = nt * 8 + 2 * c + pr;
                    float y = acc[dd][nt][half * 2 + pr] + b_s[ch];
                    float t = fminf(fmaxf(y + 3.f, 0.f), 6.f);
                    float v = valid ? y * t * (1.f / 6.f) : 0.f;
                    sv[nt * 2 + pr] += v;
                    s2[nt * 2 + pr] += v * v;
                }
            }
        }
    }

    // reduce across the 8 lanes sharing c: xor 4, 8, 16
    #pragma unroll
    for (int i = 0; i < 8; i++) {
        #pragma unroll
        for (int off = 4; off <= 16; off <<= 1) {
            sv[i] += __shfl_xor_sync(0xffffffffu, sv[i], off);
            s2[i] += __shfl_xor_sync(0xffffffffu, s2[i], off);
        }
    }
    if (grp == 0) {
        #pragma unroll
        for (int i = 0; i < 8; i++) {
            int ch = (i >> 1) * 8 + 2 * c + (i & 1);
            atomicAdd(&s_red[ch],      sv[i]);
            atomicAdd(&s_red[32 + ch], s2[i]);
        }
    }
    __syncthreads();
    if (tid < 64) atomicAdd(&g_sums[b * 64 + tid], s_red[tid]);
}

// ---------------------------------------------------------------------------
// Finalize: GroupNorm stats from channel sums -> [B, C]
// ---------------------------------------------------------------------------
__global__ void finalize_kernel(const float* __restrict__ gn_w,
                                const float* __restrict__ gn_b,
                                float* __restrict__ out)
{
    int i = threadIdx.x;
    if (i >= B_ * COUT) return;
    int b = i >> 5, c = i & 31;
    int g = c >> 3;
    const float* s = &g_sums[b * 64];
    float S1 = 0.f, S2 = 0.f;
    #pragma unroll
    for (int j = 0; j < 8; j++) {
        S1 += s[g * 8 + j];
        S2 += s[32 + g * 8 + j];
    }
    float invNg = 1.f / (8.f * NPOS_F);
    float mean  = S1 * invNg;
    float var   = S2 * invNg - mean * mean;
    float rinv  = rsqrtf(var + EPSGN);
    float mc    = s[c] * (1.f / NPOS_F);
    out[i] = (mc - mean) * rinv * gn_w[c] + gn_b[c];
}

// ---------------------------------------------------------------------------
extern "C" void kernel_launch(void* const* d_in, const int* in_sizes, int n_in,
                              void* d_out, int out_size)
{
    const float* x      = (const float*)d_in[0];
    const float* weight = (const float*)d_in[1];
    const float* bias   = (const float*)d_in[2];
    const float* gn_w   = (const float*)d_in[3];
    const float* gn_b   = (const float*)d_in[4];
    float* out = (float*)d_out;

    const int smem_bytes = SMEM_WORDS * 4;   // 37632
    cudaFuncSetAttribute(conv_mma_kernel,
                         cudaFuncAttributeMaxDynamicSharedMemorySize, smem_bytes);

    prep_kernel<<<1, 1024>>>(weight);

    dim3 grid(12, 23, B_);   // (12 h-chunks, 23 d-pairs, 16 b)
    conv_mma_kernel<<<grid, TPB, smem_bytes>>>(x, bias);

    finalize_kernel<<<1, 512>>>(gn_w, gn_b, out);
}

// round 17
// speedup vs baseline: 1.2920x; 1.2920x over previous
#include <cuda_runtime.h>
#include <cuda_fp16.h>

// Problem constants
#define B_    16
#define CIN   8
#define COUT  32
#define DIN   48
#define DOUT  46
#define TPB   384     // 12 warps: 3 w-tiles x 4 h-rows
#define NPAIR 112     // 28 half-chunks (27 taps + 1 pad) x 4 ic-pairs
#define NCHK  14      // k16 chunks
#define WSTR  40      // w2_s slot stride (32 + 8 pad, conflict-free B)
#define ND    2       // d-outputs per warp

// x2 tile: [icpair 4][plane 4][hh 6][col 50] + 8 pad words per icpair
// XIC2 = 1208: 1208 mod 32 = 24 -> icp groups at {0,24,16,8}: conflict-free af
#define XCW   50
#define XPL   (6 * XCW)       // 300 (plane stride)
#define XIC2  1208            // 4*300 + 8 pad
#define X2SZ  (4 * XIC2)      // 4832

// smem word offsets
#define SO_X2   0
#define SO_W    X2SZ                   // 4832
#define WSZ     (NPAIR * WSTR)         // 4480
#define SO_ROFF (SO_W + WSZ)           // 9312
#define SO_B    (SO_ROFF + NPAIR)      // 9424
#define SO_RED  (SO_B + 32)            // 9456
#define SMEM_WORDS (SO_RED + 64)       // 9520 -> 38080 bytes

#define NPOS_F (46.f * 46.f * 46.f)
#define EPSGN  1e-5f

typedef unsigned long long u64;

__device__ float    g_sums[B_ * 64];
__device__ unsigned g_w2[WSZ];   // packed half2 weights [slot][40]

__device__ __forceinline__ unsigned packh2(float a, float b) {
    __half2 h = __floats2half2_rn(a, b);   // lo=a, hi=b
    return *(unsigned*)&h;
}

__device__ __forceinline__ void mma_f16(float* c, const unsigned* a, const unsigned* b) {
    asm volatile(
        "mma.sync.aligned.m16n8k16.row.col.f32.f16.f16.f32 "
        "{%0,%1,%2,%3}, {%4,%5,%6,%7}, {%8,%9}, {%0,%1,%2,%3};"
        : "+f"(c[0]), "+f"(c[1]), "+f"(c[2]), "+f"(c[3])
        : "r"(a[0]), "r"(a[1]), "r"(a[2]), "r"(a[3]), "r"(b[0]), "r"(b[1]));
}

// ---------------------------------------------------------------------------
// Slot map: s in [0,112): cc = s>>3, idx = s&7, c = idx&3 (= ic-pair),
// half = idx>>2; tap(s) = 2*cc + half. Weights pack ic {2c, 2c+1} at tap.
// ---------------------------------------------------------------------------
__global__ void prep_kernel(const float* __restrict__ w)
{
    int t = threadIdx.x;
    if (t < B_ * 64) g_sums[t] = 0.f;
    for (int i = t; i < WSZ; i += 1024) {
        int n = i % WSTR;
        int s = i / WSTR;
        int c   = s & 3;
        int tap = 2 * (s >> 3) + ((s >> 2) & 1);
        float wa = 0.f, wb = 0.f;
        if (tap < 27 && n < COUT) {
            wa = w[(n * CIN + 2 * c)     * 27 + tap];
            wb = w[(n * CIN + 2 * c + 1) * 27 + tap];
        }
        g_w2[i] = packh2(wa, wb);
    }
}

// ---------------------------------------------------------------------------
// Implicit-GEMM conv3d (fp16 m16n8k16), conflict-free A-side LDS, occ=2
// grid = (12 h-chunks, 23 d-pairs, 16 b), block = 384
// ---------------------------------------------------------------------------
extern __shared__ unsigned smem_u[];

__global__ void __launch_bounds__(TPB, 2)
conv_mma_kernel(const float* __restrict__ x, const float* __restrict__ bias)
{
    unsigned* x2_s   = smem_u + SO_X2;
    unsigned* w2_s   = smem_u + SO_W;
    unsigned* roff_s = smem_u + SO_ROFF;
    float* b_s   = (float*)(smem_u + SO_B);
    float* s_red = (float*)(smem_u + SO_RED);

    const int b   = blockIdx.z;
    const int db  = blockIdx.y;          // d outputs 2db, 2db+1 (< 46)
    const int h0  = blockIdx.x * 4;
    const int tid = threadIdx.x;

    // --- weights: coalesced uint4 copy (1120 uint4) ---
    {
        const uint4* src = (const uint4*)g_w2;
        uint4* dst = (uint4*)w2_s;
        for (int i = tid; i < WSZ / 4; i += TPB) dst[i] = src[i];
    }
    // --- roff table: slot -> x2 offset (icp term keeps conflict-freedom) ---
    if (tid < NPAIR) {
        int icp = tid & 3;
        int tap = 2 * (tid >> 3) + ((tid >> 2) & 1);
        unsigned o = (unsigned)(icp * XIC2);
        if (tap < 27) {
            int kd = tap / 9, r2 = tap - 9 * kd;
            o += (unsigned)(kd * XPL + (r2 / 3) * XCW + (r2 % 3));
        }
        roff_s[tid] = o;
    }
    if (tid < 64) s_red[tid] = 0.f;
    if (tid < COUT) b_s[tid] = bias[tid];

    // --- x2 tile: 96 rows x 4 col-chunks, all 384 threads active ---
    {
        int row = tid >> 2, q4 = tid & 3;    // row = icp*24 + pl*6 + hh
        int icp = row / 24, rem = row % 24;
        int pl  = rem / 6,  hh  = rem % 6;
        int hg  = h0 + hh;
        int dg  = 2 * db + pl;               // <= 47, in-bounds
        float xa[12], xb[12];
        if (hg < DIN) {
            const float4* rowA = (const float4*)
                &x[(((b * CIN + 2 * icp)     * DIN + dg) * DIN + hg) * DIN] + 3 * q4;
            const float4* rowB = (const float4*)
                &x[(((b * CIN + 2 * icp + 1) * DIN + dg) * DIN + hg) * DIN] + 3 * q4;
            #pragma unroll
            for (int q = 0; q < 3; q++) {
                float4 va = rowA[q], vb = rowB[q];
                xa[4*q] = va.x; xa[4*q+1] = va.y; xa[4*q+2] = va.z; xa[4*q+3] = va.w;
                xb[4*q] = vb.x; xb[4*q+1] = vb.y; xb[4*q+2] = vb.z; xb[4*q+3] = vb.w;
            }
        } else {
            #pragma unroll
            for (int q = 0; q < 12; q++) { xa[q] = 0.f; xb[q] = 0.f; }
        }
        u64* base = (u64*)&x2_s[icp * XIC2 + rem * XCW];   // even word base
        u64* dst  = base + 6 * q4;
        #pragma unroll
        for (int j = 0; j < 6; j++) {
            unsigned lo = packh2(xa[2*j],     xb[2*j]);
            unsigned hi = packh2(xa[2*j + 1], xb[2*j + 1]);
            dst[j] = (u64)lo | ((u64)hi << 32);
        }
        if (q4 == 3) dst[6] = 0ull;          // cols 48,49 pad
    }
    __syncthreads();

    const int wid = tid >> 5, lane = tid & 31;
    const int grp = lane >> 2, c = lane & 3;
    const int wt  = wid % 3,  hp = wid / 3;     // w-tile (16 wide), h-row
    const int w0  = wt * 16;

    float acc[ND][4][4];
    #pragma unroll
    for (int m = 0; m < ND; m++)
        #pragma unroll
        for (int n = 0; n < 4; n++)
            #pragma unroll
            for (int k = 0; k < 4; k++) acc[m][n][k] = 0.f;

    const int xbase = hp * XCW + w0 + grp;

    // ---- single K loop: 14 chunks; af LDS conflict-free by construction ----
    #pragma unroll 2
    for (int cc = 0; cc < NCHK; cc++) {
        const int P1 = 8 * cc + c;
        const int o1 = (int)roff_s[P1];
        const int o2 = (int)roff_s[P1 + 4];

        unsigned bf[4][2];
        #pragma unroll
        for (int nt = 0; nt < 4; nt++) {
            bf[nt][0] = w2_s[P1 * WSTR + nt * 8 + grp];
            bf[nt][1] = w2_s[(P1 + 4) * WSTR + nt * 8 + grp];
        }
        const int A1 = xbase + o1;
        const int A2 = xbase + o2;
        #pragma unroll
        for (int dd = 0; dd < ND; dd++) {
            const int o = dd * XPL;
            unsigned af[4];
            af[0] = x2_s[A1 + o];
            af[1] = x2_s[A1 + o + 8];
            af[2] = x2_s[A2 + o];
            af[3] = x2_s[A2 + o + 8];
            #pragma unroll
            for (int nt = 0; nt < 4; nt++)
                mma_f16(acc[dd][nt], af, bf[nt]);
        }
    }

    // --- bias + hardswish + masked channel sums (d always valid) ---
    const bool vh0  = (h0 + hp) < DOUT;
    const bool vw[2] = { vh0 && (w0 + grp) < DOUT, vh0 && (w0 + grp + 8) < DOUT };

    float sv[8], s2[8];
    #pragma unroll
    for (int i = 0; i < 8; i++) { sv[i] = 0.f; s2[i] = 0.f; }

    #pragma unroll
    for (int dd = 0; dd < ND; dd++) {
        #pragma unroll
        for (int half = 0; half < 2; half++) {
            const bool valid = vw[half];
            #pragma unroll
            for (int nt = 0; nt < 4; nt++) {
                #pragma unroll
                for (int pr = 0; pr < 2; pr++) {
                    int ch = nt * 8 + 2 * c + pr;
                    float y = acc[dd][nt][half * 2 + pr] + b_s[ch];
                    float t = fminf(fmaxf(y + 3.f, 0.f), 6.f);
                    float v = valid ? y * t * (1.f / 6.f) : 0.f;
                    sv[nt * 2 + pr] += v;
                    s2[nt * 2 + pr] += v * v;
                }
            }
        }
    }

    // reduce across the 8 lanes sharing c: xor 4, 8, 16
    #pragma unroll
    for (int i = 0; i < 8; i++) {
        #pragma unroll
        for (int off = 4; off <= 16; off <<= 1) {
            sv[i] += __shfl_xor_sync(0xffffffffu, sv[i], off);
            s2[i] += __shfl_xor_sync(0xffffffffu, s2[i], off);
        }
    }
    if (grp == 0) {
        #pragma unroll
        for (int i = 0; i < 8; i++) {
            int ch = (i >> 1) * 8 + 2 * c + (i & 1);
            atomicAdd(&s_red[ch],      sv[i]);
            atomicAdd(&s_red[32 + ch], s2[i]);
        }
    }
    __syncthreads();
    if (tid < 64) atomicAdd(&g_sums[b * 64 + tid], s_red[tid]);
}

// ---------------------------------------------------------------------------
// Finalize: GroupNorm stats from channel sums -> [B, C]
// ---------------------------------------------------------------------------
__global__ void finalize_kernel(const float* __restrict__ gn_w,
                                const float* __restrict__ gn_b,
                                float* __restrict__ out)
{
    int i = threadIdx.x;
    if (i >= B_ * COUT) return;
    int b = i >> 5, c = i & 31;
    int g = c >> 3;
    const float* s = &g_sums[b * 64];
    float S1 = 0.f, S2 = 0.f;
    #pragma unroll
    for (int j = 0; j < 8; j++) {
        S1 += s[g * 8 + j];
        S2 += s[32 + g * 8 + j];
    }
    float invNg = 1.f / (8.f * NPOS_F);
    float mean  = S1 * invNg;
    float var   = S2 * invNg - mean * mean;
    float rinv  = rsqrtf(var + EPSGN);
    float mc    = s[c] * (1.f / NPOS_F);
    out[i] = (mc - mean) * rinv * gn_w[c] + gn_b[c];
}

// ---------------------------------------------------------------------------
extern "C" void kernel_launch(void* const* d_in, const int* in_sizes, int n_in,
                              void* d_out, int out_size)
{
    const float* x      = (const float*)d_in[0];
    const float* weight = (const float*)d_in[1];
    const float* bias   = (const float*)d_in[2];
    const float* gn_w   = (const float*)d_in[3];
    const float* gn_b   = (const float*)d_in[4];
    float* out = (float*)d_out;

    const int smem_bytes = SMEM_WORDS * 4;   // 38080
    cudaFuncSetAttribute(conv_mma_kernel,
                         cudaFuncAttributeMaxDynamicSharedMemorySize, smem_bytes);

    prep_kernel<<<1, 1024>>>(weight);

    dim3 grid(12, 23, B_);   // (12 h-chunks, 23 d-pairs, 16 b)
    conv_mma_kernel<<<grid, TPB, smem_bytes>>>(x, bias);

    finalize_kernel<<<1, 512>>>(gn_w, gn_b, out);
}